// round 13
// baseline (speedup 1.0000x reference)
#include <cuda_runtime.h>
#include <math.h>

#define TN   4096
#define NENV 32
#define TT   128
#define HID  256
#define NBLK_LSTM 128

typedef unsigned long long ull;

__device__ __forceinline__ ull pk2(float lo, float hi) {
    ull r; asm("mov.b64 %0,{%1,%2};" : "=l"(r) : "f"(lo), "f"(hi)); return r;
}
__device__ __forceinline__ void unpk2(ull v, float& lo, float& hi) {
    asm("mov.b64 {%0,%1},%2;" : "=f"(lo), "=f"(hi) : "l"(v));
}
__device__ __forceinline__ ull ffma2(ull a, ull b, ull c) {
    ull d; asm("fma.rn.f32x2 %0,%1,%2,%3;" : "=l"(d) : "l"(a), "l"(b), "l"(c)); return d;
}
__device__ __forceinline__ float psum(ull v) {
    float lo, hi; unpk2(v, lo, hi); return lo + hi;
}

// ---------------- scratch ----------------
__device__ float g_out1[TN * 32 * 288];   // row stride 18, 16 rows
__device__ float g_out2[TN * 64 * 36];
__device__ float g_out3[TN * 1024];
__device__ float g_feats[TN * 512];
__device__ float g_gi[TN * 1024];         // gate inputs [t*32+r][G]
__device__ float g_gt[TN * 1024];         // gate inputs transposed [t][G][r]
__device__ float g_outs[TN * HID];
__device__ ull   g_hbuf[2][128 * NENV];
__device__ float g_w3p[64 * 768];
__device__ int   g_flags[NBLK_LSTM];

// ---- conv1 v4: (TN,4,64,64)->(TN,32,15x15 in 16x18 rows), k8 s4 ----
__global__ __launch_bounds__(256, 2) void conv1_kernel(
        const float* __restrict__ x, const float* __restrict__ w,
        const float* __restrict__ b, float* __restrict__ out) {
    extern __shared__ float xs[];   // x: 256 rows * 17 quads = 17408 fl; w: 8192 fl
    float* ws = xs + 17408;
    const int tid = threadIdx.x, img = blockIdx.x;
    const float4* xg = (const float4*)(x + (size_t)img * 16384);
    const float inv = 1.0f / 255.0f;
    for (int i = tid; i < 4096; i += 256) {
        float4 v = xg[i];
        v.x *= inv; v.y *= inv; v.z *= inv; v.w *= inv;
        const int r = i >> 4, c = i & 15;
        ((float4*)xs)[r * 17 + (c ^ ((r >> 2) & 3))] = v;
    }
    if (tid < 256) ((float4*)xs)[tid * 17 + 16] = make_float4(0.f, 0.f, 0.f, 0.f);
    for (int i = tid; i < 2048; i += 256)
        ((float4*)ws)[i] = ((const float4*)w)[i];
    __syncthreads();

    const int ocg = tid >> 6, u = tid & 63;
    if (u >= 60) return;
    const int py = u >> 2, xq = u & 3;

    ull acc[4][8];
#pragma unroll
    for (int q = 0; q < 4; q++)
#pragma unroll
        for (int j = 0; j < 8; j++) acc[q][j] = 0ull;

    const ulonglong2* wb = (const ulonglong2*)ws + ocg * 8 * 64;
#pragma unroll 1
    for (int ik = 0; ik < 32; ik++) {
        const int ic = ik >> 3, ky = ik & 7;
        const int row = ic * 64 + py * 4 + ky;
        const int key = (row >> 2) & 3;
        const ulonglong2* xrow = (const ulonglong2*)xs + row * 17;
        ull xv[10];
#pragma unroll
        for (int i = 0; i < 5; i++) {
            const int c = 4 * xq + i;
            const int cs = (c < 16) ? (c ^ key) : 16;
            const ulonglong2 t = xrow[cs];
            xv[2 * i] = t.x; xv[2 * i + 1] = t.y;
        }
        const ulonglong2* wk = wb + ik * 2;
#pragma unroll
        for (int j = 0; j < 8; j++) {
            const ulonglong2 w0 = wk[j * 64];
            const ulonglong2 w1 = wk[j * 64 + 1];
#pragma unroll
            for (int q = 0; q < 4; q++) {
                ull s = acc[q][j];
                s = ffma2(xv[2 * q],     w0.x, s);
                s = ffma2(xv[2 * q + 1], w0.y, s);
                s = ffma2(xv[2 * q + 2], w1.x, s);
                s = ffma2(xv[2 * q + 3], w1.y, s);
                acc[q][j] = s;
            }
        }
    }
    float* base = out + (size_t)img * 9216 + py * 18;
#pragma unroll
    for (int j = 0; j < 8; j++) {
        const int oc = ocg * 8 + j;
        const float bias = __ldg(&b[oc]);
#pragma unroll
        for (int q = 0; q < 4; q++) {
            const int px = 4 * xq + q;
            if (px < 15) {
                float v = psum(acc[q][j]) + bias;
                base[oc * 288 + px] = v > 0.f ? v : 0.f;
            }
        }
    }
}

// ---- conv2 v3: two ic-chunks, smem x + broadcast smem weights ----
__global__ __launch_bounds__(256, 2) void conv2_kernel(
        const float* __restrict__ in, const float* __restrict__ w,
        const float* __restrict__ b, float* __restrict__ out) {
    extern __shared__ float sm2[];
    float* xs = sm2;            // 2 * 4616 floats
    float* ws = sm2 + 9232;     // 64 oc * 256 floats
    const int tid = threadIdx.x, blk = blockIdx.x;
    const float4* in4 = (const float4*)(in + (size_t)blk * 18432);
    const float4* w4g = (const float4*)w;
    float4* xs4 = (float4*)xs;
    float4* ws4 = (float4*)ws;

    const int ocg = tid >> 5, lane = tid & 31;
    const int img_l = lane / 12, v = lane % 12;
    const int oy = v >> 1, ox0 = (v & 1) * 3;
    const bool active = lane < 24;

    ull a[3][8];
#pragma unroll
    for (int s = 0; s < 3; s++)
#pragma unroll
        for (int j = 0; j < 8; j++) a[s][j] = 0ull;

#pragma unroll 1
    for (int ch = 0; ch < 2; ch++) {
        __syncthreads();
        for (int i = tid; i < 2304; i += 256) {
            const int im = i / 1152, rem = i - im * 1152;
            xs4[im * 1154 + rem] = in4[im * 2304 + ch * 1152 + rem];
        }
        for (int i = tid; i < 4096; i += 256) {
            const int oc = i >> 6, r = i & 63;
            ws4[oc * 64 + r] = w4g[oc * 128 + ch * 64 + r];
        }
        __syncthreads();
        if (active) {
            const float* xb = xs + img_l * 4616 + oy * 36 + ox0 * 2;
            const ulonglong2* wsk = (const ulonglong2*)ws;
#pragma unroll 1
            for (int ic = 0; ic < 16; ic++) {
#pragma unroll
                for (int ky = 0; ky < 4; ky++) {
                    const float* xr = xb + ic * 288 + ky * 18;
                    const ull p0 = ((const ull*)xr)[0];
                    const ull p1 = ((const ull*)xr)[1];
                    const ull p2 = ((const ull*)xr)[2];
                    const ull p3 = ((const ull*)xr)[3];
                    const int wbase = (ocg * 8) * 64 + ic * 4 + ky;
#pragma unroll
                    for (int j = 0; j < 8; j++) {
                        const ulonglong2 wv = wsk[wbase + j * 64];
                        a[0][j] = ffma2(p0, wv.x, a[0][j]);
                        a[0][j] = ffma2(p1, wv.y, a[0][j]);
                        a[1][j] = ffma2(p1, wv.x, a[1][j]);
                        a[1][j] = ffma2(p2, wv.y, a[1][j]);
                        a[2][j] = ffma2(p2, wv.x, a[2][j]);
                        a[2][j] = ffma2(p3, wv.y, a[2][j]);
                    }
                }
            }
        }
    }
    if (!active) return;
    const int img = blk * 2 + img_l;
    float* op = out + (size_t)img * 2304 + oy * 6 + ox0;
#pragma unroll
    for (int j = 0; j < 8; j++) {
        const int oc = ocg * 8 + j;
        const float bias = __ldg(&b[oc]);
#pragma unroll
        for (int s = 0; s < 3; s++) {
            float vv = psum(a[s][j]) + bias;
            op[oc * 36 + s] = vv > 0.f ? vv : 0.f;
        }
    }
}

// ---- conv3 weight prep (merged): pad kx 3->4, pad lane = 0 ----
__global__ void prep_w3(const float* __restrict__ w) {
    const int i = blockIdx.x * 256 + threadIdx.x;
    if (i >= 64 * 768) return;
    const int oc = i / 768, r = i % 768;
    const int ic = r / 12, q = r % 12;
    const int ky = q >> 2, kx = q & 3;
    g_w3p[i] = (kx < 3) ? w[oc * 576 + ic * 9 + ky * 3 + kx] : 0.f;
}

// ---- conv3 v7: 8 imgs/block, 4 ic-chunks, broadcast smem weights ----
// warp = ocg (8 oc), lane = (img, out-row); 4 pos x 8 oc per thread.
__global__ __launch_bounds__(256, 2) void conv3_kernel(
        const float* __restrict__ in, const float* __restrict__ w3p,
        const float* __restrict__ b, float* __restrict__ out) {
    extern __shared__ float sm3[];
    float* xs = sm3;              // 8 imgs * 1160 fl (16 ic dual-copy rows)
    float* ws = sm3 + 9280;       // 64 oc * 192 fl (chunk)
    const int tid = threadIdx.x, blk = blockIdx.x;
    const float* gin = in + (size_t)blk * 8 * 2304;
    const float4* w4g = (const float4*)w3p;
    float4* ws4 = (float4*)ws;

    const int wp = tid >> 5, lane = tid & 31;
    const int img_l = lane >> 2, row = lane & 3;
    const int ocbase = wp * 8;

    ull acc[4][8];
#pragma unroll
    for (int p = 0; p < 4; p++)
#pragma unroll
        for (int j = 0; j < 8; j++) acc[p][j] = 0ull;

#pragma unroll 1
    for (int ch = 0; ch < 4; ch++) {
        __syncthreads();
        // stage x chunk: 8 imgs x 16 ic x 36, dual-copy rows [x0..x5 | x1..x5,_]
        for (int i = tid; i < 4608; i += 256) {
            const int im = i / 576, rem = i - im * 576;
            const int icl = rem / 36, rr = rem - icl * 36;
            const int rw = rr / 6, col = rr - rw * 6;
            const float v = gin[(size_t)im * 2304 + (ch * 16 + icl) * 36 + rr];
            float* rb = xs + im * 1160 + icl * 72 + rw * 12;
            rb[col] = v;
            if (col > 0) rb[col + 5] = v;
        }
        for (int i = tid; i < 768; i += 256) {
            const int im = i / 96, rem = i - im * 96;
            xs[im * 1160 + rem * 12 + 11] = 0.f;
        }
        // stage w chunk: ws[oc][0..191] = w3p[oc*768 + ch*192 ..]
        for (int i = tid; i < 3072; i += 256) {
            const int oc = i / 48, r = i - oc * 48;
            ws4[oc * 48 + r] = w4g[oc * 192 + ch * 48 + r];
        }
        __syncthreads();

        const float* xb = xs + img_l * 1160 + row * 12;
        const ulonglong2* wbch = (const ulonglong2*)ws + ocbase * 48;
#pragma unroll 1
        for (int icl = 0; icl < 16; icl++) {
            const float* xc = xb + icl * 72;
#pragma unroll
            for (int ky = 0; ky < 3; ky++) {
                const float* r = xc + ky * 12;
                const ull a01 = ((const ull*)r)[0];
                const ull a23 = ((const ull*)r)[1];
                const ull a45 = ((const ull*)r)[2];
                const ull b12 = ((const ull*)r)[3];
                const ull b34 = ((const ull*)r)[4];
                const ull b5z = ((const ull*)r)[5];
                const ulonglong2* wk = wbch + icl * 3 + ky;
#pragma unroll
                for (int j = 0; j < 8; j++) {
                    const ulonglong2 wv = wk[j * 48];   // broadcast LDS
                    acc[0][j] = ffma2(a01, wv.x, acc[0][j]);
                    acc[0][j] = ffma2(a23, wv.y, acc[0][j]);
                    acc[1][j] = ffma2(b12, wv.x, acc[1][j]);
                    acc[1][j] = ffma2(b34, wv.y, acc[1][j]);
                    acc[2][j] = ffma2(a23, wv.x, acc[2][j]);
                    acc[2][j] = ffma2(a45, wv.y, acc[2][j]);
                    acc[3][j] = ffma2(b34, wv.x, acc[3][j]);
                    acc[3][j] = ffma2(b5z, wv.y, acc[3][j]);
                }
            }
        }
    }
    const int img = blk * 8 + img_l;
    float* op = out + (size_t)img * 1024 + row * 4;
#pragma unroll
    for (int j = 0; j < 8; j++) {
        const int oc = ocbase + j;
        const float bias = __ldg(&b[oc]);
        float4 v;
        v.x = psum(acc[0][j]) + bias; v.x = v.x > 0.f ? v.x : 0.f;
        v.y = psum(acc[1][j]) + bias; v.y = v.y > 0.f ? v.y : 0.f;
        v.z = psum(acc[2][j]) + bias; v.z = v.z > 0.f ? v.z : 0.f;
        v.w = psum(acc[3][j]) + bias; v.w = v.w > 0.f ? v.w : 0.f;
        *(float4*)(op + oc * 16) = v;
    }
}

// ---- GEMM NT: 128x128 tile, 256 thr, 8x8 micro; mode 0 plain / 1 relu ----
__global__ __launch_bounds__(256, 2) void gemm_nt(
        const float* __restrict__ A, const float* __restrict__ B,
        const float* __restrict__ bias1, const float* __restrict__ bias2,
        float* __restrict__ C, int M, int N, int K, int mode) {
    __shared__ __align__(16) float As[2][16][128];
    __shared__ __align__(16) float Bs[2][16][128];
    const int tid = threadIdx.x;
    const int m0 = blockIdx.y * 128, n0 = blockIdx.x * 128;
    const int row = tid >> 1, half = tid & 1;
    const int ty = tid >> 4, tx = tid & 15;
    const float* Ap = A + (size_t)(m0 + row) * K + half * 8;
    const float* Bp = B + (size_t)(n0 + row) * K + half * 8;

    ull acc[8][4];
#pragma unroll
    for (int i = 0; i < 8; i++)
#pragma unroll
        for (int j = 0; j < 4; j++) acc[i][j] = 0ull;

    {
        const float4 a0 = *(const float4*)(Ap), a1 = *(const float4*)(Ap + 4);
        const float4 b0 = *(const float4*)(Bp), b1 = *(const float4*)(Bp + 4);
        const float af[8] = {a0.x,a0.y,a0.z,a0.w,a1.x,a1.y,a1.z,a1.w};
        const float bf[8] = {b0.x,b0.y,b0.z,b0.w,b1.x,b1.y,b1.z,b1.w};
#pragma unroll
        for (int e = 0; e < 8; e++) {
            As[0][half * 8 + e][row] = af[e];
            Bs[0][half * 8 + e][row] = bf[e];
        }
    }
    __syncthreads();

    int buf = 0;
    for (int k0 = 0; k0 < K; k0 += 16) {
        const bool more = (k0 + 16) < K;
        float4 a0, a1, b0, b1;
        if (more) {
            a0 = *(const float4*)(Ap + k0 + 16); a1 = *(const float4*)(Ap + k0 + 20);
            b0 = *(const float4*)(Bp + k0 + 16); b1 = *(const float4*)(Bp + k0 + 20);
        }
#pragma unroll
        for (int kk = 0; kk < 16; kk++) {
            const float4 av0 = *(const float4*)&As[buf][kk][ty * 8];
            const float4 av1 = *(const float4*)&As[buf][kk][ty * 8 + 4];
            const ulonglong2 bv0 = *(const ulonglong2*)&Bs[buf][kk][tx * 8];
            const ulonglong2 bv1 = *(const ulonglong2*)&Bs[buf][kk][tx * 8 + 4];
            ull ad[8];
            ad[0] = pk2(av0.x, av0.x); ad[1] = pk2(av0.y, av0.y);
            ad[2] = pk2(av0.z, av0.z); ad[3] = pk2(av0.w, av0.w);
            ad[4] = pk2(av1.x, av1.x); ad[5] = pk2(av1.y, av1.y);
            ad[6] = pk2(av1.z, av1.z); ad[7] = pk2(av1.w, av1.w);
            const ull bd[4] = {bv0.x, bv0.y, bv1.x, bv1.y};
#pragma unroll
            for (int i = 0; i < 8; i++)
#pragma unroll
                for (int j = 0; j < 4; j++)
                    acc[i][j] = ffma2(ad[i], bd[j], acc[i][j]);
        }
        if (more) {
            const int nb = buf ^ 1;
            const float af[8] = {a0.x,a0.y,a0.z,a0.w,a1.x,a1.y,a1.z,a1.w};
            const float bf[8] = {b0.x,b0.y,b0.z,b0.w,b1.x,b1.y,b1.z,b1.w};
#pragma unroll
            for (int e = 0; e < 8; e++) {
                As[nb][half * 8 + e][row] = af[e];
                Bs[nb][half * 8 + e][row] = bf[e];
            }
        }
        __syncthreads();
        buf ^= 1;
    }

    const int n = n0 + tx * 8;
    float bb[8];
#pragma unroll
    for (int j = 0; j < 8; j++) {
        float v = bias1 ? bias1[n + j] : 0.f;
        if (bias2) v += bias2[n + j];
        bb[j] = v;
    }
#pragma unroll
    for (int i = 0; i < 8; i++) {
        float r[8];
#pragma unroll
        for (int j = 0; j < 4; j++) {
            float lo, hi; unpk2(acc[i][j], lo, hi);
            r[2 * j] = lo + bb[2 * j]; r[2 * j + 1] = hi + bb[2 * j + 1];
            if (mode == 1) {
                r[2 * j] = r[2 * j] > 0.f ? r[2 * j] : 0.f;
                r[2 * j + 1] = r[2 * j + 1] > 0.f ? r[2 * j + 1] : 0.f;
            }
        }
        float* cp = &C[(size_t)(m0 + ty * 8 + i) * N + n];
        *(float4*)(cp)     = make_float4(r[0], r[1], r[2], r[3]);
        *(float4*)(cp + 4) = make_float4(r[4], r[5], r[6], r[7]);
    }
}

// ---- gi transpose: [t*32+r][G] -> [t][G][r] ----
__global__ void gi_transpose(const float* __restrict__ gi, float* __restrict__ gt) {
    __shared__ float tile[32][33];
    const int t = blockIdx.x, gb = blockIdx.y;
    const int tx = threadIdx.x, ty = threadIdx.y;
    for (int rr = ty; rr < 32; rr += 8)
        tile[rr][tx] = gi[(size_t)(t * 32 + rr) * 1024 + gb * 32 + tx];
    __syncthreads();
    for (int gg = ty; gg < 32; gg += 8)
        gt[(size_t)(t * 1024 + gb * 32 + gg) * 32 + tx] = tile[tx][gg];
}

__global__ void init_h_kernel(const float* __restrict__ h0) {
    const int i = blockIdx.x * blockDim.x + threadIdx.x;
    const int r = i / HID, k = i % HID;
    ((float*)&g_hbuf[0][(k >> 1) * NENV + r])[k & 1] = h0[i];
}

// ---- persistent LSTM v2: warp = (gate-quad, k-quarter); 4-gate x reuse ----
__global__ __launch_bounds__(256) void lstm_kernel(
        const float* __restrict__ gt, const float* __restrict__ done,
        const float* __restrict__ c0, const float* __restrict__ wh,
        float* __restrict__ outs) {
    __shared__ __align__(16) ull hs2[128 * NENV];
    __shared__ __align__(16) ull wt[128 * 8];
    __shared__ float gsmP[4][8][NENV];
    __shared__ float gsm[8 * NENV];
    __shared__ float cs[2 * NENV];
    __shared__ float ms[NENV];
    __shared__ int s_base;

    const int tid = threadIdx.x, blk = blockIdx.x;
    const int w = tid >> 5, lane = tid & 31;

    {
        const int G = (w & 3) * HID + 2 * blk + (w >> 2);
        const ull* whrow = (const ull*)(wh + (size_t)G * HID);
#pragma unroll
        for (int it = 0; it < 4; it++) {
            const int kp = lane + it * 32;
            wt[kp * 8 + w] = whrow[kp];
        }
    }
    if (tid < 64) {
        const int hcl = tid >> 5, r = tid & 31;
        cs[tid] = c0[r * HID + 2 * blk + hcl];
    }
    if (tid == 0) s_base = *(volatile int*)&g_flags[blk];
    __syncthreads();
    const int base = s_base;

    const int gq = w & 1, kq = w >> 1;
    const int kbase = kq * 32;
    const int gR = tid >> 5, envR = tid & 31;
    const int GR = (gR & 3) * HID + 2 * blk + (gR >> 2);

    float giv = __ldg(&gt[(size_t)GR * 32 + envR]);
    for (int t = 0; t < TT; t++) {
        const float4* hsrc = (const float4*)g_hbuf[t & 1];
        if (tid < NENV) ms[tid] = 1.0f - done[t * NENV + tid];
#pragma unroll
        for (int i = 0; i < 8; i++)
            ((float4*)hs2)[tid + i * 256] = __ldcg(&hsrc[tid + i * 256]);
        __syncthreads();

        ull a0 = 0ull, a1 = 0ull, a2 = 0ull, a3 = 0ull;
#pragma unroll 8
        for (int i = 0; i < 32; i++) {
            const int kp = kbase + i;
            const ull xv = hs2[kp * NENV + lane];
            const ulonglong2 wp0 = *(const ulonglong2*)&wt[kp * 8 + gq * 4];
            const ulonglong2 wp1 = *(const ulonglong2*)&wt[kp * 8 + gq * 4 + 2];
            a0 = ffma2(xv, wp0.x, a0);
            a1 = ffma2(xv, wp0.y, a1);
            a2 = ffma2(xv, wp1.x, a2);
            a3 = ffma2(xv, wp1.y, a3);
        }
        gsmP[kq][gq * 4 + 0][lane] = psum(a0);
        gsmP[kq][gq * 4 + 1][lane] = psum(a1);
        gsmP[kq][gq * 4 + 2][lane] = psum(a2);
        gsmP[kq][gq * 4 + 3][lane] = psum(a3);
        __syncthreads();

        {
            const float s = gsmP[0][gR][envR] + gsmP[1][gR][envR]
                          + gsmP[2][gR][envR] + gsmP[3][gR][envR];
            gsm[gR * NENV + envR] = giv + ms[envR] * s;
        }
        __syncthreads();

        ull* hdst = g_hbuf[(t + 1) & 1];
        float hval = 0.f; int r_ = 0, hc_ = 0;
        if (tid < 64) {
            const int hcl = tid >> 5, r = tid & 31;
            const float gi_ = gsm[(hcl * 4 + 0) * NENV + r];
            const float gf_ = gsm[(hcl * 4 + 1) * NENV + r];
            const float gg_ = gsm[(hcl * 4 + 2) * NENV + r];
            const float go_ = gsm[(hcl * 4 + 3) * NENV + r];
            const float iv = 1.f / (1.f + expf(-gi_));
            const float fv = 1.f / (1.f + expf(-gf_));
            const float ov = 1.f / (1.f + expf(-go_));
            const float gv = tanhf(gg_);
            const float c = fv * (cs[tid] * ms[r]) + iv * gv;
            cs[tid] = c;
            hval = ov * tanhf(c);
            r_ = r; hc_ = 2 * blk + hcl;
            ((float*)&hdst[blk * NENV + r])[hcl] = hval;
            __threadfence();
        }
        __syncthreads();
        const int tgt = base + t + 1;
        if (tid == 0) *(volatile int*)&g_flags[blk] = tgt;
        if (t + 1 < TT) giv = __ldg(&gt[(size_t)((t + 1) * 1024 + GR) * 32 + envR]);
        if (tid < 64) outs[(size_t)(t * NENV + r_) * HID + hc_] = hval;
        if (w == 0) {
#pragma unroll
            for (int q = 0; q < 4; q++)
                while (*(volatile int*)&g_flags[lane + q * 32] - tgt < 0)
                    __nanosleep(32);
        }
        __syncthreads();
    }
}

// ---- actor/critic heads ----
__global__ void heads_kernel(const float* __restrict__ outs,
                             const float* __restrict__ aw, const float* __restrict__ ab,
                             const float* __restrict__ cw, const float* __restrict__ cb,
                             float* __restrict__ out) {
    __shared__ float hsm[32 * HID];
    const int tid = threadIdx.x, row0 = blockIdx.x * 32;
    for (int i = tid; i < 32 * HID; i += 256) hsm[i] = outs[(size_t)row0 * HID + i];
    __syncthreads();
    for (int o = tid; o < 32 * 19; o += 256) {
        const int r = o / 19, j = o % 19;
        const float* wp = (j < 18) ? (aw + j * HID) : cw;
        const float bias = (j < 18) ? ab[j] : cb[0];
        const float4* h4 = (const float4*)(hsm + r * HID);
        const float4* w4 = (const float4*)wp;
        float acc = 0.f;
#pragma unroll 8
        for (int k = 0; k < HID / 4; k++) {
            const float4 hv = h4[k];
            const float4 wv = __ldg(&w4[k]);
            acc += hv.x*wv.x + hv.y*wv.y + hv.z*wv.z + hv.w*wv.w;
        }
        out[(size_t)(row0 + r) * 19 + j] = acc + bias;
    }
}

// ---- launch ----
extern "C" void kernel_launch(void* const* d_in, const int* in_sizes, int n_in,
                              void* d_out, int out_size) {
    const float* x    = (const float*)d_in[0];
    const float* done = (const float*)d_in[1];
    const float* h0   = (const float*)d_in[2];
    const float* c0   = (const float*)d_in[3];
    const float* c1w  = (const float*)d_in[4];
    const float* c1b  = (const float*)d_in[5];
    const float* c2w  = (const float*)d_in[6];
    const float* c2b  = (const float*)d_in[7];
    const float* c3w  = (const float*)d_in[8];
    const float* c3b  = (const float*)d_in[9];
    const float* fcw  = (const float*)d_in[10];
    const float* fcb  = (const float*)d_in[11];
    const float* wi   = (const float*)d_in[12];
    const float* wh   = (const float*)d_in[13];
    const float* bi   = (const float*)d_in[14];
    const float* bh   = (const float*)d_in[15];
    const float* aw   = (const float*)d_in[16];
    const float* ab   = (const float*)d_in[17];
    const float* cw   = (const float*)d_in[18];
    const float* cb   = (const float*)d_in[19];
    float* out = (float*)d_out;

    cudaFuncSetAttribute(conv1_kernel, cudaFuncAttributeMaxDynamicSharedMemorySize, 102400);
    cudaFuncSetAttribute(conv2_kernel, cudaFuncAttributeMaxDynamicSharedMemorySize, 102464);
    cudaFuncSetAttribute(conv3_kernel, cudaFuncAttributeMaxDynamicSharedMemorySize, 86272);

    float* out1;  cudaGetSymbolAddress((void**)&out1,  g_out1);
    float* out2;  cudaGetSymbolAddress((void**)&out2,  g_out2);
    float* out3;  cudaGetSymbolAddress((void**)&out3,  g_out3);
    float* feats; cudaGetSymbolAddress((void**)&feats, g_feats);
    float* gi;    cudaGetSymbolAddress((void**)&gi,    g_gi);
    float* gt;    cudaGetSymbolAddress((void**)&gt,    g_gt);
    float* outs;  cudaGetSymbolAddress((void**)&outs,  g_outs);
    float* w3p;   cudaGetSymbolAddress((void**)&w3p,   g_w3p);

    conv1_kernel<<<TN, 256, 102400>>>(x, c1w, c1b, out1);
    prep_w3<<<192, 256>>>(c3w);
    conv2_kernel<<<TN / 2, 256, 102464>>>(out1, c2w, c2b, out2);
    conv3_kernel<<<TN / 8, 256, 86272>>>(out2, w3p, c3b, out3);   // 4th: profiled
    gemm_nt<<<dim3(512 / 128, TN / 128), 256>>>(out3, fcw, fcb, nullptr, feats, TN, 512, 1024, 1);
    gemm_nt<<<dim3(1024 / 128, TN / 128), 256>>>(feats, wi, bi, bh, gi, TN, 1024, 512, 0);
    gi_transpose<<<dim3(TT, 32), dim3(32, 8)>>>(gi, gt);
    init_h_kernel<<<32, 256>>>(h0);
    lstm_kernel<<<NBLK_LSTM, 256>>>(gt, done, c0, wh, outs);
    heads_kernel<<<TN / 32, 256>>>(outs, aw, ab, cw, cb, out);
}

// round 15
// speedup vs baseline: 1.0515x; 1.0515x over previous
#include <cuda_runtime.h>
#include <math.h>

#define TN   4096
#define NENV 32
#define TT   128
#define HID  256
#define NBLK_LSTM 128

typedef unsigned long long ull;

__device__ __forceinline__ ull pk2(float lo, float hi) {
    ull r; asm("mov.b64 %0,{%1,%2};" : "=l"(r) : "f"(lo), "f"(hi)); return r;
}
__device__ __forceinline__ void unpk2(ull v, float& lo, float& hi) {
    asm("mov.b64 {%0,%1},%2;" : "=f"(lo), "=f"(hi) : "l"(v));
}
__device__ __forceinline__ ull ffma2(ull a, ull b, ull c) {
    ull d; asm("fma.rn.f32x2 %0,%1,%2,%3;" : "=l"(d) : "l"(a), "l"(b), "l"(c)); return d;
}
__device__ __forceinline__ float psum(ull v) {
    float lo, hi; unpk2(v, lo, hi); return lo + hi;
}
__device__ __forceinline__ float sig_fast(float x) {
    return __fdividef(1.f, 1.f + __expf(-x));
}
__device__ __forceinline__ float tanh_fast(float x) {
    return 1.f - 2.f * __fdividef(1.f, __expf(2.f * x) + 1.f);
}

// ---------------- scratch ----------------
__device__ float g_out1[TN * 32 * 288];   // row stride 18, 16 rows
__device__ float g_out2[TN * 64 * 36];
__device__ float g_out3[TN * 1024];
__device__ float g_feats[TN * 512];
__device__ float g_gi[TN * 1024];         // gate inputs [t*32+r][G]
__device__ float g_gt[TN * 1024];         // gate inputs transposed [t][G][r]
__device__ float g_outs[TN * HID];
__device__ ull   g_hbuf[2][128 * NENV];
__device__ float g_w3p[64 * 768];
__device__ int   g_flags[NBLK_LSTM];

// ---- conv1 v4: (TN,4,64,64)->(TN,32,15x15 in 16x18 rows), k8 s4 ----
__global__ __launch_bounds__(256, 2) void conv1_kernel(
        const float* __restrict__ x, const float* __restrict__ w,
        const float* __restrict__ b, float* __restrict__ out) {
    extern __shared__ float xs[];   // x: 17408 fl; w: 8192 fl
    float* ws = xs + 17408;
    const int tid = threadIdx.x, img = blockIdx.x;
    const float4* xg = (const float4*)(x + (size_t)img * 16384);
    const float inv = 1.0f / 255.0f;
    for (int i = tid; i < 4096; i += 256) {
        float4 v = xg[i];
        v.x *= inv; v.y *= inv; v.z *= inv; v.w *= inv;
        const int r = i >> 4, c = i & 15;
        ((float4*)xs)[r * 17 + (c ^ ((r >> 2) & 3))] = v;
    }
    if (tid < 256) ((float4*)xs)[tid * 17 + 16] = make_float4(0.f, 0.f, 0.f, 0.f);
    for (int i = tid; i < 2048; i += 256)
        ((float4*)ws)[i] = ((const float4*)w)[i];
    __syncthreads();

    const int ocg = tid >> 6, u = tid & 63;
    if (u >= 60) return;
    const int py = u >> 2, xq = u & 3;

    ull acc[4][8];
#pragma unroll
    for (int q = 0; q < 4; q++)
#pragma unroll
        for (int j = 0; j < 8; j++) acc[q][j] = 0ull;

    const ulonglong2* wb = (const ulonglong2*)ws + ocg * 8 * 64;
#pragma unroll 1
    for (int ik = 0; ik < 32; ik++) {
        const int ic = ik >> 3, ky = ik & 7;
        const int row = ic * 64 + py * 4 + ky;
        const int key = (row >> 2) & 3;
        const ulonglong2* xrow = (const ulonglong2*)xs + row * 17;
        ull xv[10];
#pragma unroll
        for (int i = 0; i < 5; i++) {
            const int c = 4 * xq + i;
            const int cs = (c < 16) ? (c ^ key) : 16;
            const ulonglong2 t = xrow[cs];
            xv[2 * i] = t.x; xv[2 * i + 1] = t.y;
        }
        const ulonglong2* wk = wb + ik * 2;
#pragma unroll
        for (int j = 0; j < 8; j++) {
            const ulonglong2 w0 = wk[j * 64];
            const ulonglong2 w1 = wk[j * 64 + 1];
#pragma unroll
            for (int q = 0; q < 4; q++) {
                ull s = acc[q][j];
                s = ffma2(xv[2 * q],     w0.x, s);
                s = ffma2(xv[2 * q + 1], w0.y, s);
                s = ffma2(xv[2 * q + 2], w1.x, s);
                s = ffma2(xv[2 * q + 3], w1.y, s);
                acc[q][j] = s;
            }
        }
    }
    float* base = out + (size_t)img * 9216 + py * 18;
#pragma unroll
    for (int j = 0; j < 8; j++) {
        const int oc = ocg * 8 + j;
        const float bias = __ldg(&b[oc]);
#pragma unroll
        for (int q = 0; q < 4; q++) {
            const int px = 4 * xq + q;
            if (px < 15) {
                float v = psum(acc[q][j]) + bias;
                base[oc * 288 + px] = v > 0.f ? v : 0.f;
            }
        }
    }
}

// ---- conv2 v3: two ic-chunks, smem x + broadcast smem weights ----
__global__ __launch_bounds__(256, 2) void conv2_kernel(
        const float* __restrict__ in, const float* __restrict__ w,
        const float* __restrict__ b, float* __restrict__ out) {
    extern __shared__ float sm2[];
    float* xs = sm2;            // 2 * 4616 floats
    float* ws = sm2 + 9232;     // 64 oc * 256 floats
    const int tid = threadIdx.x, blk = blockIdx.x;
    const float4* in4 = (const float4*)(in + (size_t)blk * 18432);
    const float4* w4g = (const float4*)w;
    float4* xs4 = (float4*)xs;
    float4* ws4 = (float4*)ws;

    const int ocg = tid >> 5, lane = tid & 31;
    const int img_l = lane / 12, v = lane % 12;
    const int oy = v >> 1, ox0 = (v & 1) * 3;
    const bool active = lane < 24;

    ull a[3][8];
#pragma unroll
    for (int s = 0; s < 3; s++)
#pragma unroll
        for (int j = 0; j < 8; j++) a[s][j] = 0ull;

#pragma unroll 1
    for (int ch = 0; ch < 2; ch++) {
        __syncthreads();
        for (int i = tid; i < 2304; i += 256) {
            const int im = i / 1152, rem = i - im * 1152;
            xs4[im * 1154 + rem] = in4[im * 2304 + ch * 1152 + rem];
        }
        for (int i = tid; i < 4096; i += 256) {
            const int oc = i >> 6, r = i & 63;
            ws4[oc * 64 + r] = w4g[oc * 128 + ch * 64 + r];
        }
        __syncthreads();
        if (active) {
            const float* xb = xs + img_l * 4616 + oy * 36 + ox0 * 2;
            const ulonglong2* wsk = (const ulonglong2*)ws;
#pragma unroll 1
            for (int ic = 0; ic < 16; ic++) {
#pragma unroll
                for (int ky = 0; ky < 4; ky++) {
                    const float* xr = xb + ic * 288 + ky * 18;
                    const ull p0 = ((const ull*)xr)[0];
                    const ull p1 = ((const ull*)xr)[1];
                    const ull p2 = ((const ull*)xr)[2];
                    const ull p3 = ((const ull*)xr)[3];
                    const int wbase = (ocg * 8) * 64 + ic * 4 + ky;
#pragma unroll
                    for (int j = 0; j < 8; j++) {
                        const ulonglong2 wv = wsk[wbase + j * 64];
                        a[0][j] = ffma2(p0, wv.x, a[0][j]);
                        a[0][j] = ffma2(p1, wv.y, a[0][j]);
                        a[1][j] = ffma2(p1, wv.x, a[1][j]);
                        a[1][j] = ffma2(p2, wv.y, a[1][j]);
                        a[2][j] = ffma2(p2, wv.x, a[2][j]);
                        a[2][j] = ffma2(p3, wv.y, a[2][j]);
                    }
                }
            }
        }
    }
    if (!active) return;
    const int img = blk * 2 + img_l;
    float* op = out + (size_t)img * 2304 + oy * 6 + ox0;
#pragma unroll
    for (int j = 0; j < 8; j++) {
        const int oc = ocg * 8 + j;
        const float bias = __ldg(&b[oc]);
#pragma unroll
        for (int s = 0; s < 3; s++) {
            float vv = psum(a[s][j]) + bias;
            op[oc * 36 + s] = vv > 0.f ? vv : 0.f;
        }
    }
}

// ---- conv3 weight prep: pad kx 3->4, pad lane = 0 ----
__global__ void prep_w3(const float* __restrict__ w) {
    const int i = blockIdx.x * 256 + threadIdx.x;
    if (i >= 64 * 768) return;
    const int oc = i / 768, r = i % 768;
    const int ic = r / 12, q = r % 12;
    const int ky = q >> 2, kx = q & 3;
    g_w3p[i] = (kx < 3) ? w[oc * 576 + ic * 9 + ky * 3 + kx] : 0.f;
}

// ---- conv3 v5: dual-copy rows, __ldg weights, 4 imgs/block ----
__global__ __launch_bounds__(256, 3) void conv3_kernel(
        const float* __restrict__ in, const float* __restrict__ w3p,
        const float* __restrict__ b, float* __restrict__ out) {
    extern __shared__ float xs[];   // 4 * 4616 floats
    const int tid = threadIdx.x, blk = blockIdx.x;
    const float* gin = in + (size_t)blk * 9216;
    for (int i = tid; i < 9216; i += 256) {
        const int img_l = i / 2304, rem = i - img_l * 2304;
        const int ic = rem / 36, rr = rem - ic * 36;
        const int row = rr / 6, col = rr - row * 6;
        const float v = gin[i];
        float* rb = xs + img_l * 4616 + ic * 72 + row * 12;
        rb[col] = v;
        if (col > 0) rb[col + 5] = v;
    }
    for (int i = tid; i < 1536; i += 256) {
        const int img_l = i / 384, rem = i - img_l * 384;
        xs[img_l * 4616 + rem * 12 + 11] = 0.f;
    }
    __syncthreads();

    const int w = tid >> 5, lane = tid & 31;
    const int ochalf = lane >> 4, rem16 = lane & 15;
    const int img_l = rem16 >> 2, row = rem16 & 3;
    const int ocbase = w * 8 + ochalf * 4;

    ull acc[4][4];
#pragma unroll
    for (int p = 0; p < 4; p++)
#pragma unroll
        for (int j = 0; j < 4; j++) acc[p][j] = 0ull;

    const float* xb = xs + img_l * 4616 + row * 12;
    const ulonglong2* wb = (const ulonglong2*)w3p + ocbase * 192;
#pragma unroll 1
    for (int ic = 0; ic < 64; ic++) {
        const float* xc = xb + ic * 72;
#pragma unroll
        for (int ky = 0; ky < 3; ky++) {
            const float* r = xc + ky * 12;
            const ull a01 = ((const ull*)r)[0];
            const ull a23 = ((const ull*)r)[1];
            const ull a45 = ((const ull*)r)[2];
            const ull b12 = ((const ull*)r)[3];
            const ull b34 = ((const ull*)r)[4];
            const ull b5z = ((const ull*)r)[5];
            const ulonglong2* wk = wb + ic * 3 + ky;
#pragma unroll
            for (int j = 0; j < 4; j++) {
                const ulonglong2 wv = __ldg(wk + j * 192);
                acc[0][j] = ffma2(a01, wv.x, acc[0][j]);
                acc[0][j] = ffma2(a23, wv.y, acc[0][j]);
                acc[1][j] = ffma2(b12, wv.x, acc[1][j]);
                acc[1][j] = ffma2(b34, wv.y, acc[1][j]);
                acc[2][j] = ffma2(a23, wv.x, acc[2][j]);
                acc[2][j] = ffma2(a45, wv.y, acc[2][j]);
                acc[3][j] = ffma2(b34, wv.x, acc[3][j]);
                acc[3][j] = ffma2(b5z, wv.y, acc[3][j]);
            }
        }
    }
    const int img = blk * 4 + img_l;
    float* op = out + (size_t)img * 1024 + row * 4;
#pragma unroll
    for (int j = 0; j < 4; j++) {
        const int oc = ocbase + j;
        const float bias = __ldg(&b[oc]);
        float4 v;
        v.x = psum(acc[0][j]) + bias; v.x = v.x > 0.f ? v.x : 0.f;
        v.y = psum(acc[1][j]) + bias; v.y = v.y > 0.f ? v.y : 0.f;
        v.z = psum(acc[2][j]) + bias; v.z = v.z > 0.f ? v.z : 0.f;
        v.w = psum(acc[3][j]) + bias; v.w = v.w > 0.f ? v.w : 0.f;
        *(float4*)(op + oc * 16) = v;
    }
}

// ---- GEMM NT: 128x128 tile, 256 thr, 8x8 micro; mode 0 plain / 1 relu ----
__global__ __launch_bounds__(256, 2) void gemm_nt(
        const float* __restrict__ A, const float* __restrict__ B,
        const float* __restrict__ bias1, const float* __restrict__ bias2,
        float* __restrict__ C, int M, int N, int K, int mode) {
    __shared__ __align__(16) float As[2][16][128];
    __shared__ __align__(16) float Bs[2][16][128];
    const int tid = threadIdx.x;
    const int m0 = blockIdx.y * 128, n0 = blockIdx.x * 128;
    const int row = tid >> 1, half = tid & 1;
    const int ty = tid >> 4, tx = tid & 15;
    const float* Ap = A + (size_t)(m0 + row) * K + half * 8;
    const float* Bp = B + (size_t)(n0 + row) * K + half * 8;

    ull acc[8][4];
#pragma unroll
    for (int i = 0; i < 8; i++)
#pragma unroll
        for (int j = 0; j < 4; j++) acc[i][j] = 0ull;

    {
        const float4 a0 = *(const float4*)(Ap), a1 = *(const float4*)(Ap + 4);
        const float4 b0 = *(const float4*)(Bp), b1 = *(const float4*)(Bp + 4);
        const float af[8] = {a0.x,a0.y,a0.z,a0.w,a1.x,a1.y,a1.z,a1.w};
        const float bf[8] = {b0.x,b0.y,b0.z,b0.w,b1.x,b1.y,b1.z,b1.w};
#pragma unroll
        for (int e = 0; e < 8; e++) {
            As[0][half * 8 + e][row] = af[e];
            Bs[0][half * 8 + e][row] = bf[e];
        }
    }
    __syncthreads();

    int buf = 0;
    for (int k0 = 0; k0 < K; k0 += 16) {
        const bool more = (k0 + 16) < K;
        float4 a0, a1, b0, b1;
        if (more) {
            a0 = *(const float4*)(Ap + k0 + 16); a1 = *(const float4*)(Ap + k0 + 20);
            b0 = *(const float4*)(Bp + k0 + 16); b1 = *(const float4*)(Bp + k0 + 20);
        }
#pragma unroll
        for (int kk = 0; kk < 16; kk++) {
            const float4 av0 = *(const float4*)&As[buf][kk][ty * 8];
            const float4 av1 = *(const float4*)&As[buf][kk][ty * 8 + 4];
            const ulonglong2 bv0 = *(const ulonglong2*)&Bs[buf][kk][tx * 8];
            const ulonglong2 bv1 = *(const ulonglong2*)&Bs[buf][kk][tx * 8 + 4];
            ull ad[8];
            ad[0] = pk2(av0.x, av0.x); ad[1] = pk2(av0.y, av0.y);
            ad[2] = pk2(av0.z, av0.z); ad[3] = pk2(av0.w, av0.w);
            ad[4] = pk2(av1.x, av1.x); ad[5] = pk2(av1.y, av1.y);
            ad[6] = pk2(av1.z, av1.z); ad[7] = pk2(av1.w, av1.w);
            const ull bd[4] = {bv0.x, bv0.y, bv1.x, bv1.y};
#pragma unroll
            for (int i = 0; i < 8; i++)
#pragma unroll
                for (int j = 0; j < 4; j++)
                    acc[i][j] = ffma2(ad[i], bd[j], acc[i][j]);
        }
        if (more) {
            const int nb = buf ^ 1;
            const float af[8] = {a0.x,a0.y,a0.z,a0.w,a1.x,a1.y,a1.z,a1.w};
            const float bf[8] = {b0.x,b0.y,b0.z,b0.w,b1.x,b1.y,b1.z,b1.w};
#pragma unroll
            for (int e = 0; e < 8; e++) {
                As[nb][half * 8 + e][row] = af[e];
                Bs[nb][half * 8 + e][row] = bf[e];
            }
        }
        __syncthreads();
        buf ^= 1;
    }

    const int n = n0 + tx * 8;
    float bb[8];
#pragma unroll
    for (int j = 0; j < 8; j++) {
        float v = bias1 ? bias1[n + j] : 0.f;
        if (bias2) v += bias2[n + j];
        bb[j] = v;
    }
#pragma unroll
    for (int i = 0; i < 8; i++) {
        float r[8];
#pragma unroll
        for (int j = 0; j < 4; j++) {
            float lo, hi; unpk2(acc[i][j], lo, hi);
            r[2 * j] = lo + bb[2 * j]; r[2 * j + 1] = hi + bb[2 * j + 1];
            if (mode == 1) {
                r[2 * j] = r[2 * j] > 0.f ? r[2 * j] : 0.f;
                r[2 * j + 1] = r[2 * j + 1] > 0.f ? r[2 * j + 1] : 0.f;
            }
        }
        float* cp = &C[(size_t)(m0 + ty * 8 + i) * N + n];
        *(float4*)(cp)     = make_float4(r[0], r[1], r[2], r[3]);
        *(float4*)(cp + 4) = make_float4(r[4], r[5], r[6], r[7]);
    }
}

// ---- gi transpose: [t*32+r][G] -> [t][G][r] ----
__global__ void gi_transpose(const float* __restrict__ gi, float* __restrict__ gt) {
    __shared__ float tile[32][33];
    const int t = blockIdx.x, gb = blockIdx.y;
    const int tx = threadIdx.x, ty = threadIdx.y;
    for (int rr = ty; rr < 32; rr += 8)
        tile[rr][tx] = gi[(size_t)(t * 32 + rr) * 1024 + gb * 32 + tx];
    __syncthreads();
    for (int gg = ty; gg < 32; gg += 8)
        gt[(size_t)(t * 1024 + gb * 32 + gg) * 32 + tx] = tile[tx][gg];
}

__global__ void init_h_kernel(const float* __restrict__ h0) {
    const int i = blockIdx.x * blockDim.x + threadIdx.x;
    const int r = i / HID, k = i % HID;
    ((float*)&g_hbuf[0][(k >> 1) * NENV + r])[k & 1] = h0[i];
}

// ---- persistent LSTM v3: warp = k-eighth x all 8 gates; fused reduce+activation;
//      fast-exp activations; nanosleep-backoff flag barrier; dynamic smem ----
__global__ __launch_bounds__(256) void lstm_kernel(
        const float* __restrict__ gt, const float* __restrict__ done,
        const float* __restrict__ c0, const float* __restrict__ wh,
        float* __restrict__ outs) {
    extern __shared__ char smL[];
    ull*   hs2  = (ull*)smL;                     // 32768 B: [kp][env] packed pairs
    ull*   wt   = (ull*)(smL + 32768);           //  8192 B: [kp][g]
    float* gsmP = (float*)(smL + 40960);         //  8192 B: [q][g][r] = q*256+g*32+r
    float* cs   = (float*)(smL + 49152);         //   256 B
    float* ms   = (float*)(smL + 49408);         //   128 B
    __shared__ int s_base;

    const int tid = threadIdx.x, blk = blockIdx.x;
    const int w = tid >> 5, lane = tid & 31;

    {   // build wt: warp w owns gate column w
        const int G = (w & 3) * HID + 2 * blk + (w >> 2);
        const ull* whrow = (const ull*)(wh + (size_t)G * HID);
#pragma unroll
        for (int it = 0; it < 4; it++) {
            const int kp = lane + it * 32;
            wt[kp * 8 + w] = whrow[kp];
        }
    }
    const int hcl = (tid >> 5) & 1, r = lane;    // activation mapping (tid<64)
    if (tid < 64) cs[tid] = c0[r * HID + 2 * blk + hcl];
    if (tid == 0) s_base = *(volatile int*)&g_flags[blk];
    __syncthreads();
    const int base = s_base;

    const int kb = w * 16;                        // this warp's 16 kp
    int Gj[4]; float giv[4];
    if (tid < 64) {
#pragma unroll
        for (int j = 0; j < 4; j++) {
            const int g = hcl * 4 + j;
            Gj[j] = (g & 3) * HID + 2 * blk + (g >> 2);
            giv[j] = __ldg(&gt[(size_t)Gj[j] * 32 + r]);
        }
    }

    for (int t = 0; t < TT; t++) {
        const float4* hsrc = (const float4*)g_hbuf[t & 1];
        if (tid < NENV) ms[tid] = 1.0f - done[t * NENV + tid];
#pragma unroll
        for (int i = 0; i < 8; i++)
            ((float4*)hs2)[tid + i * 256] = __ldcg(&hsrc[tid + i * 256]);
        __syncthreads();                                   // s1

        // dot: each thread, 16 kp x 8 gates, x loaded once per kp
        ull a[8];
#pragma unroll
        for (int g = 0; g < 8; g++) a[g] = 0ull;
#pragma unroll 4
        for (int i = 0; i < 16; i++) {
            const int kp = kb + i;
            const ull xv = hs2[kp * NENV + lane];
            const ulonglong2* wr = (const ulonglong2*)&wt[kp * 8];
            const ulonglong2 w01 = wr[0], w23 = wr[1], w45 = wr[2], w67 = wr[3];
            a[0] = ffma2(xv, w01.x, a[0]); a[1] = ffma2(xv, w01.y, a[1]);
            a[2] = ffma2(xv, w23.x, a[2]); a[3] = ffma2(xv, w23.y, a[3]);
            a[4] = ffma2(xv, w45.x, a[4]); a[5] = ffma2(xv, w45.y, a[5]);
            a[6] = ffma2(xv, w67.x, a[6]); a[7] = ffma2(xv, w67.y, a[7]);
        }
#pragma unroll
        for (int g = 0; g < 8; g++)
            gsmP[w * 256 + g * 32 + lane] = psum(a[g]);
        __syncthreads();                                   // s2

        ull* hdst = g_hbuf[(t + 1) & 1];
        float hval = 0.f;
        if (tid < 64) {
            const float m = ms[r];
            float gate[4];
#pragma unroll
            for (int j = 0; j < 4; j++) {
                const int g = hcl * 4 + j;
                float s = 0.f;
#pragma unroll
                for (int q = 0; q < 8; q++) s += gsmP[q * 256 + g * 32 + r];
                gate[j] = giv[j] + m * s;
            }
            const float iv = sig_fast(gate[0]);
            const float fv = sig_fast(gate[1]);
            const float gv = tanh_fast(gate[2]);
            const float ov = sig_fast(gate[3]);
            const float c = fv * (cs[tid] * m) + iv * gv;
            cs[tid] = c;
            hval = ov * tanh_fast(c);
            ((float*)&hdst[blk * NENV + r])[hcl] = hval;
            __threadfence();
        }
        __syncthreads();                                   // s3
        const int tgt = base + t + 1;
        if (tid == 0) *(volatile int*)&g_flags[blk] = tgt;
        if (tid < 64) {
            outs[(size_t)(t * NENV + r) * HID + 2 * blk + hcl] = hval;
            if (t + 1 < TT) {
#pragma unroll
                for (int j = 0; j < 4; j++)
                    giv[j] = __ldg(&gt[(size_t)((t + 1) * 1024 + Gj[j]) * 32 + r]);
            }
        }
        if (w == 0) {
#pragma unroll
            for (int q = 0; q < 4; q++)
                while (*(volatile int*)&g_flags[lane + q * 32] - tgt < 0)
                    __nanosleep(20);
        }
        __syncthreads();                                   // s4
    }
}

// ---- actor/critic heads ----
__global__ void heads_kernel(const float* __restrict__ outs,
                             const float* __restrict__ aw, const float* __restrict__ ab,
                             const float* __restrict__ cw, const float* __restrict__ cb,
                             float* __restrict__ out) {
    __shared__ float hsm[32 * HID];
    const int tid = threadIdx.x, row0 = blockIdx.x * 32;
    for (int i = tid; i < 32 * HID; i += 256) hsm[i] = outs[(size_t)row0 * HID + i];
    __syncthreads();
    for (int o = tid; o < 32 * 19; o += 256) {
        const int r = o / 19, j = o % 19;
        const float* wp = (j < 18) ? (aw + j * HID) : cw;
        const float bias = (j < 18) ? ab[j] : cb[0];
        const float4* h4 = (const float4*)(hsm + r * HID);
        const float4* w4 = (const float4*)wp;
        float acc = 0.f;
#pragma unroll 8
        for (int k = 0; k < HID / 4; k++) {
            const float4 hv = h4[k];
            const float4 wv = __ldg(&w4[k]);
            acc += hv.x*wv.x + hv.y*wv.y + hv.z*wv.z + hv.w*wv.w;
        }
        out[(size_t)(row0 + r) * 19 + j] = acc + bias;
    }
}

// ---- launch ----
extern "C" void kernel_launch(void* const* d_in, const int* in_sizes, int n_in,
                              void* d_out, int out_size) {
    const float* x    = (const float*)d_in[0];
    const float* done = (const float*)d_in[1];
    const float* h0   = (const float*)d_in[2];
    const float* c0   = (const float*)d_in[3];
    const float* c1w  = (const float*)d_in[4];
    const float* c1b  = (const float*)d_in[5];
    const float* c2w  = (const float*)d_in[6];
    const float* c2b  = (const float*)d_in[7];
    const float* c3w  = (const float*)d_in[8];
    const float* c3b  = (const float*)d_in[9];
    const float* fcw  = (const float*)d_in[10];
    const float* fcb  = (const float*)d_in[11];
    const float* wi   = (const float*)d_in[12];
    const float* wh   = (const float*)d_in[13];
    const float* bi   = (const float*)d_in[14];
    const float* bh   = (const float*)d_in[15];
    const float* aw   = (const float*)d_in[16];
    const float* ab   = (const float*)d_in[17];
    const float* cw   = (const float*)d_in[18];
    const float* cb   = (const float*)d_in[19];
    float* out = (float*)d_out;

    cudaFuncSetAttribute(conv1_kernel, cudaFuncAttributeMaxDynamicSharedMemorySize, 102400);
    cudaFuncSetAttribute(conv2_kernel, cudaFuncAttributeMaxDynamicSharedMemorySize, 102464);
    cudaFuncSetAttribute(conv3_kernel, cudaFuncAttributeMaxDynamicSharedMemorySize, 73856);
    cudaFuncSetAttribute(lstm_kernel,  cudaFuncAttributeMaxDynamicSharedMemorySize, 49664);

    float* out1;  cudaGetSymbolAddress((void**)&out1,  g_out1);
    float* out2;  cudaGetSymbolAddress((void**)&out2,  g_out2);
    float* out3;  cudaGetSymbolAddress((void**)&out3,  g_out3);
    float* feats; cudaGetSymbolAddress((void**)&feats, g_feats);
    float* gi;    cudaGetSymbolAddress((void**)&gi,    g_gi);
    float* gt;    cudaGetSymbolAddress((void**)&gt,    g_gt);
    float* outs;  cudaGetSymbolAddress((void**)&outs,  g_outs);
    float* w3p;   cudaGetSymbolAddress((void**)&w3p,   g_w3p);

    conv1_kernel<<<TN, 256, 102400>>>(x, c1w, c1b, out1);
    prep_w3<<<192, 256>>>(c3w);
    conv2_kernel<<<TN / 2, 256, 102464>>>(out1, c2w, c2b, out2);
    conv3_kernel<<<TN / 4, 256, 73856>>>(out2, w3p, c3b, out3);   // 4th: profiled
    gemm_nt<<<dim3(512 / 128, TN / 128), 256>>>(out3, fcw, fcb, nullptr, feats, TN, 512, 1024, 1);
    gemm_nt<<<dim3(1024 / 128, TN / 128), 256>>>(feats, wi, bi, bh, gi, TN, 1024, 512, 0);
    gi_transpose<<<dim3(TT, 32), dim3(32, 8)>>>(gi, gt);
    init_h_kernel<<<32, 256>>>(h0);
    lstm_kernel<<<NBLK_LSTM, 256, 49664>>>(gt, done, c0, wh, outs);
    heads_kernel<<<TN / 32, 256>>>(outs, aw, ab, cw, cb, out);
}

// round 16
// speedup vs baseline: 1.0565x; 1.0047x over previous
#include <cuda_runtime.h>
#include <math.h>

#define TN   4096
#define NENV 32
#define TT   128
#define HID  256
#define NBLK_LSTM 128

typedef unsigned long long ull;

__device__ __forceinline__ ull pk2(float lo, float hi) {
    ull r; asm("mov.b64 %0,{%1,%2};" : "=l"(r) : "f"(lo), "f"(hi)); return r;
}
__device__ __forceinline__ void unpk2(ull v, float& lo, float& hi) {
    asm("mov.b64 {%0,%1},%2;" : "=f"(lo), "=f"(hi) : "l"(v));
}
__device__ __forceinline__ ull ffma2(ull a, ull b, ull c) {
    ull d; asm("fma.rn.f32x2 %0,%1,%2,%3;" : "=l"(d) : "l"(a), "l"(b), "l"(c)); return d;
}
__device__ __forceinline__ float psum(ull v) {
    float lo, hi; unpk2(v, lo, hi); return lo + hi;
}
__device__ __forceinline__ float sig_fast(float x) {
    return __fdividef(1.f, 1.f + __expf(-x));
}
__device__ __forceinline__ float tanh_fast(float x) {
    return 1.f - 2.f * __fdividef(1.f, __expf(2.f * x) + 1.f);
}

// ---------------- scratch ----------------
__device__ float g_out1[TN * 32 * 288];   // row stride 18, 16 rows
__device__ float g_out2[TN * 64 * 36];
__device__ float g_out3[TN * 1024];
__device__ float g_feats[TN * 512];
__device__ float g_gi[TN * 1024];
__device__ float g_gt[TN * 1024];
__device__ float g_outs[TN * HID];
__device__ ull   g_hbuf[2][128 * NENV];
__device__ ull   g_w3a[64 * 192];         // (w0,w1) per (oc,ic,ky)
__device__ ull   g_w3b[64 * 192];         // (w2,0)  per (oc,ic,ky)
__device__ int   g_flags[NBLK_LSTM];

// ---- conv1 v4 ----
__global__ __launch_bounds__(256, 2) void conv1_kernel(
        const float* __restrict__ x, const float* __restrict__ w,
        const float* __restrict__ b, float* __restrict__ out) {
    extern __shared__ float xs[];
    float* ws = xs + 17408;
    const int tid = threadIdx.x, img = blockIdx.x;
    const float4* xg = (const float4*)(x + (size_t)img * 16384);
    const float inv = 1.0f / 255.0f;
    for (int i = tid; i < 4096; i += 256) {
        float4 v = xg[i];
        v.x *= inv; v.y *= inv; v.z *= inv; v.w *= inv;
        const int r = i >> 4, c = i & 15;
        ((float4*)xs)[r * 17 + (c ^ ((r >> 2) & 3))] = v;
    }
    if (tid < 256) ((float4*)xs)[tid * 17 + 16] = make_float4(0.f, 0.f, 0.f, 0.f);
    for (int i = tid; i < 2048; i += 256)
        ((float4*)ws)[i] = ((const float4*)w)[i];
    __syncthreads();

    const int ocg = tid >> 6, u = tid & 63;
    if (u >= 60) return;
    const int py = u >> 2, xq = u & 3;

    ull acc[4][8];
#pragma unroll
    for (int q = 0; q < 4; q++)
#pragma unroll
        for (int j = 0; j < 8; j++) acc[q][j] = 0ull;

    const ulonglong2* wb = (const ulonglong2*)ws + ocg * 8 * 64;
#pragma unroll 1
    for (int ik = 0; ik < 32; ik++) {
        const int ic = ik >> 3, ky = ik & 7;
        const int row = ic * 64 + py * 4 + ky;
        const int key = (row >> 2) & 3;
        const ulonglong2* xrow = (const ulonglong2*)xs + row * 17;
        ull xv[10];
#pragma unroll
        for (int i = 0; i < 5; i++) {
            const int c = 4 * xq + i;
            const int cs = (c < 16) ? (c ^ key) : 16;
            const ulonglong2 t = xrow[cs];
            xv[2 * i] = t.x; xv[2 * i + 1] = t.y;
        }
        const ulonglong2* wk = wb + ik * 2;
#pragma unroll
        for (int j = 0; j < 8; j++) {
            const ulonglong2 w0 = wk[j * 64];
            const ulonglong2 w1 = wk[j * 64 + 1];
#pragma unroll
            for (int q = 0; q < 4; q++) {
                ull s = acc[q][j];
                s = ffma2(xv[2 * q],     w0.x, s);
                s = ffma2(xv[2 * q + 1], w0.y, s);
                s = ffma2(xv[2 * q + 2], w1.x, s);
                s = ffma2(xv[2 * q + 3], w1.y, s);
                acc[q][j] = s;
            }
        }
    }
    float* base = out + (size_t)img * 9216 + py * 18;
#pragma unroll
    for (int j = 0; j < 8; j++) {
        const int oc = ocg * 8 + j;
        const float bias = __ldg(&b[oc]);
#pragma unroll
        for (int q = 0; q < 4; q++) {
            const int px = 4 * xq + q;
            if (px < 15) {
                float v = psum(acc[q][j]) + bias;
                base[oc * 288 + px] = v > 0.f ? v : 0.f;
            }
        }
    }
}

// ---- conv2 v3 ----
__global__ __launch_bounds__(256, 2) void conv2_kernel(
        const float* __restrict__ in, const float* __restrict__ w,
        const float* __restrict__ b, float* __restrict__ out) {
    extern __shared__ float sm2[];
    float* xs = sm2;
    float* ws = sm2 + 9232;
    const int tid = threadIdx.x, blk = blockIdx.x;
    const float4* in4 = (const float4*)(in + (size_t)blk * 18432);
    const float4* w4g = (const float4*)w;
    float4* xs4 = (float4*)xs;
    float4* ws4 = (float4*)ws;

    const int ocg = tid >> 5, lane = tid & 31;
    const int img_l = lane / 12, v = lane % 12;
    const int oy = v >> 1, ox0 = (v & 1) * 3;
    const bool active = lane < 24;

    ull a[3][8];
#pragma unroll
    for (int s = 0; s < 3; s++)
#pragma unroll
        for (int j = 0; j < 8; j++) a[s][j] = 0ull;

#pragma unroll 1
    for (int ch = 0; ch < 2; ch++) {
        __syncthreads();
        for (int i = tid; i < 2304; i += 256) {
            const int im = i / 1152, rem = i - im * 1152;
            xs4[im * 1154 + rem] = in4[im * 2304 + ch * 1152 + rem];
        }
        for (int i = tid; i < 4096; i += 256) {
            const int oc = i >> 6, r = i & 63;
            ws4[oc * 64 + r] = w4g[oc * 128 + ch * 64 + r];
        }
        __syncthreads();
        if (active) {
            const float* xb = xs + img_l * 4616 + oy * 36 + ox0 * 2;
            const ulonglong2* wsk = (const ulonglong2*)ws;
#pragma unroll 1
            for (int ic = 0; ic < 16; ic++) {
#pragma unroll
                for (int ky = 0; ky < 4; ky++) {
                    const float* xr = xb + ic * 288 + ky * 18;
                    const ull p0 = ((const ull*)xr)[0];
                    const ull p1 = ((const ull*)xr)[1];
                    const ull p2 = ((const ull*)xr)[2];
                    const ull p3 = ((const ull*)xr)[3];
                    const int wbase = (ocg * 8) * 64 + ic * 4 + ky;
#pragma unroll
                    for (int j = 0; j < 8; j++) {
                        const ulonglong2 wv = wsk[wbase + j * 64];
                        a[0][j] = ffma2(p0, wv.x, a[0][j]);
                        a[0][j] = ffma2(p1, wv.y, a[0][j]);
                        a[1][j] = ffma2(p1, wv.x, a[1][j]);
                        a[1][j] = ffma2(p2, wv.y, a[1][j]);
                        a[2][j] = ffma2(p2, wv.x, a[2][j]);
                        a[2][j] = ffma2(p3, wv.y, a[2][j]);
                    }
                }
            }
        }
    }
    if (!active) return;
    const int img = blk * 2 + img_l;
    float* op = out + (size_t)img * 2304 + oy * 6 + ox0;
#pragma unroll
    for (int j = 0; j < 8; j++) {
        const int oc = ocg * 8 + j;
        const float bias = __ldg(&b[oc]);
#pragma unroll
        for (int s = 0; s < 3; s++) {
            float vv = psum(a[s][j]) + bias;
            op[oc * 36 + s] = vv > 0.f ? vv : 0.f;
        }
    }
}

// ---- conv3 weight prep: split into packed (w0,w1) and (w2,0) tables ----
__global__ void prep_w3(const float* __restrict__ w) {
    const int i = blockIdx.x * 256 + threadIdx.x;
    if (i >= 64 * 192) return;
    const int oc = i / 192, r = i % 192;
    const int ic = r / 3, ky = r % 3;
    const int base = oc * 576 + ic * 9 + ky * 3;
    g_w3a[i] = pk2(w[base], w[base + 1]);
    g_w3b[i] = pk2(w[base + 2], 0.f);
}

// ---- conv3 v9: 8 imgs/block, x staged once (bank-perfect layout),
//      weights 4x ic-chunked into smem, broadcast LDS; 8 oc x 4 pos / thread ----
__global__ __launch_bounds__(256, 1) void conv3_kernel(
        const float* __restrict__ in, const ull* __restrict__ w3a,
        const ull* __restrict__ w3b, const float* __restrict__ b,
        float* __restrict__ out) {
    extern __shared__ float sm3[];
    float* xs  = sm3;                       // [ic][inrow(6)*98 + img*12 + col] 37632 fl
    ull*   wsA = (ull*)(sm3 + 37632);       // 3072 ull (chunk)
    ull*   wsB = wsA + 3072;                // 3072 ull
    const int tid = threadIdx.x, blk = blockIdx.x;
    const float* gin = in + (size_t)blk * 18432;

    // stage x once: dual-copy rows [x0..x5 | x1..x5, 0]
    for (int i = tid; i < 18432; i += 256) {
        const int img = i / 2304, rem = i - img * 2304;
        const int ic = rem / 36, rr = rem - ic * 36;
        const int inrow = rr / 6, col = rr - inrow * 6;
        const float v = gin[i];
        float* rb = xs + ic * 588 + inrow * 98 + img * 12;
        rb[col] = v;
        if (col > 0) rb[col + 5] = v;
    }
    for (int i = tid; i < 3072; i += 256) {
        const int ic = i / 48, rem = i - ic * 48;
        const int inrow = rem >> 3, img = rem & 7;
        xs[ic * 588 + inrow * 98 + img * 12 + 11] = 0.f;
    }

    const int wp = tid >> 5, lane = tid & 31;
    const int img_l = lane >> 2, row = lane & 3;
    const int ocbase = wp * 8;

    ull acc[4][8];
#pragma unroll
    for (int p = 0; p < 4; p++)
#pragma unroll
        for (int j = 0; j < 8; j++) acc[p][j] = 0ull;

#pragma unroll 1
    for (int ch = 0; ch < 4; ch++) {
        __syncthreads();
        for (int i = tid; i < 3072; i += 256) {
            const int oc = i / 48, q = i - oc * 48;
            wsA[i] = w3a[oc * 192 + ch * 48 + q];
            wsB[i] = w3b[oc * 192 + ch * 48 + q];
        }
        __syncthreads();

#pragma unroll 1
        for (int icl = 0; icl < 16; icl++) {
            const int ic = ch * 16 + icl;
            const float* xc = xs + ic * 588 + img_l * 12;
#pragma unroll
            for (int ky = 0; ky < 3; ky++) {
                const float* r = xc + (row + ky) * 98;
                const ull a01 = ((const ull*)r)[0];
                const ull a23 = ((const ull*)r)[1];
                const ull a45 = ((const ull*)r)[2];
                const ull b12 = ((const ull*)r)[3];
                const ull b34 = ((const ull*)r)[4];
                const ull b5z = ((const ull*)r)[5];
                const int widx = ocbase * 48 + icl * 3 + ky;
#pragma unroll
                for (int j = 0; j < 8; j++) {
                    const ull wa = wsA[widx + j * 48];   // broadcast LDS
                    const ull wb = wsB[widx + j * 48];
                    acc[0][j] = ffma2(a01, wa, acc[0][j]);
                    acc[0][j] = ffma2(a23, wb, acc[0][j]);
                    acc[1][j] = ffma2(b12, wa, acc[1][j]);
                    acc[1][j] = ffma2(b34, wb, acc[1][j]);
                    acc[2][j] = ffma2(a23, wa, acc[2][j]);
                    acc[2][j] = ffma2(a45, wb, acc[2][j]);
                    acc[3][j] = ffma2(b34, wa, acc[3][j]);
                    acc[3][j] = ffma2(b5z, wb, acc[3][j]);
                }
            }
        }
    }
    const int img = blk * 8 + img_l;
    float* op = out + (size_t)img * 1024 + row * 4;
#pragma unroll
    for (int j = 0; j < 8; j++) {
        const int oc = ocbase + j;
        const float bias = __ldg(&b[oc]);
        float4 v;
        v.x = psum(acc[0][j]) + bias; v.x = v.x > 0.f ? v.x : 0.f;
        v.y = psum(acc[1][j]) + bias; v.y = v.y > 0.f ? v.y : 0.f;
        v.z = psum(acc[2][j]) + bias; v.z = v.z > 0.f ? v.z : 0.f;
        v.w = psum(acc[3][j]) + bias; v.w = v.w > 0.f ? v.w : 0.f;
        *(float4*)(op + oc * 16) = v;
    }
}

// ---- GEMM NT: 128x128 tile, 256 thr, 8x8 micro; mode 0 plain / 1 relu ----
__global__ __launch_bounds__(256, 2) void gemm_nt(
        const float* __restrict__ A, const float* __restrict__ B,
        const float* __restrict__ bias1, const float* __restrict__ bias2,
        float* __restrict__ C, int M, int N, int K, int mode) {
    __shared__ __align__(16) float As[2][16][128];
    __shared__ __align__(16) float Bs[2][16][128];
    const int tid = threadIdx.x;
    const int m0 = blockIdx.y * 128, n0 = blockIdx.x * 128;
    const int row = tid >> 1, half = tid & 1;
    const int ty = tid >> 4, tx = tid & 15;
    const float* Ap = A + (size_t)(m0 + row) * K + half * 8;
    const float* Bp = B + (size_t)(n0 + row) * K + half * 8;

    ull acc[8][4];
#pragma unroll
    for (int i = 0; i < 8; i++)
#pragma unroll
        for (int j = 0; j < 4; j++) acc[i][j] = 0ull;

    {
        const float4 a0 = *(const float4*)(Ap), a1 = *(const float4*)(Ap + 4);
        const float4 b0 = *(const float4*)(Bp), b1 = *(const float4*)(Bp + 4);
        const float af[8] = {a0.x,a0.y,a0.z,a0.w,a1.x,a1.y,a1.z,a1.w};
        const float bf[8] = {b0.x,b0.y,b0.z,b0.w,b1.x,b1.y,b1.z,b1.w};
#pragma unroll
        for (int e = 0; e < 8; e++) {
            As[0][half * 8 + e][row] = af[e];
            Bs[0][half * 8 + e][row] = bf[e];
        }
    }
    __syncthreads();

    int buf = 0;
    for (int k0 = 0; k0 < K; k0 += 16) {
        const bool more = (k0 + 16) < K;
        float4 a0, a1, b0, b1;
        if (more) {
            a0 = *(const float4*)(Ap + k0 + 16); a1 = *(const float4*)(Ap + k0 + 20);
            b0 = *(const float4*)(Bp + k0 + 16); b1 = *(const float4*)(Bp + k0 + 20);
        }
#pragma unroll
        for (int kk = 0; kk < 16; kk++) {
            const float4 av0 = *(const float4*)&As[buf][kk][ty * 8];
            const float4 av1 = *(const float4*)&As[buf][kk][ty * 8 + 4];
            const ulonglong2 bv0 = *(const ulonglong2*)&Bs[buf][kk][tx * 8];
            const ulonglong2 bv1 = *(const ulonglong2*)&Bs[buf][kk][tx * 8 + 4];
            ull ad[8];
            ad[0] = pk2(av0.x, av0.x); ad[1] = pk2(av0.y, av0.y);
            ad[2] = pk2(av0.z, av0.z); ad[3] = pk2(av0.w, av0.w);
            ad[4] = pk2(av1.x, av1.x); ad[5] = pk2(av1.y, av1.y);
            ad[6] = pk2(av1.z, av1.z); ad[7] = pk2(av1.w, av1.w);
            const ull bd[4] = {bv0.x, bv0.y, bv1.x, bv1.y};
#pragma unroll
            for (int i = 0; i < 8; i++)
#pragma unroll
                for (int j = 0; j < 4; j++)
                    acc[i][j] = ffma2(ad[i], bd[j], acc[i][j]);
        }
        if (more) {
            const int nb = buf ^ 1;
            const float af[8] = {a0.x,a0.y,a0.z,a0.w,a1.x,a1.y,a1.z,a1.w};
            const float bf[8] = {b0.x,b0.y,b0.z,b0.w,b1.x,b1.y,b1.z,b1.w};
#pragma unroll
            for (int e = 0; e < 8; e++) {
                As[nb][half * 8 + e][row] = af[e];
                Bs[nb][half * 8 + e][row] = bf[e];
            }
        }
        __syncthreads();
        buf ^= 1;
    }

    const int n = n0 + tx * 8;
    float bb[8];
#pragma unroll
    for (int j = 0; j < 8; j++) {
        float v = bias1 ? bias1[n + j] : 0.f;
        if (bias2) v += bias2[n + j];
        bb[j] = v;
    }
#pragma unroll
    for (int i = 0; i < 8; i++) {
        float r[8];
#pragma unroll
        for (int j = 0; j < 4; j++) {
            float lo, hi; unpk2(acc[i][j], lo, hi);
            r[2 * j] = lo + bb[2 * j]; r[2 * j + 1] = hi + bb[2 * j + 1];
            if (mode == 1) {
                r[2 * j] = r[2 * j] > 0.f ? r[2 * j] : 0.f;
                r[2 * j + 1] = r[2 * j + 1] > 0.f ? r[2 * j + 1] : 0.f;
            }
        }
        float* cp = &C[(size_t)(m0 + ty * 8 + i) * N + n];
        *(float4*)(cp)     = make_float4(r[0], r[1], r[2], r[3]);
        *(float4*)(cp + 4) = make_float4(r[4], r[5], r[6], r[7]);
    }
}

// ---- gi transpose ----
__global__ void gi_transpose(const float* __restrict__ gi, float* __restrict__ gt) {
    __shared__ float tile[32][33];
    const int t = blockIdx.x, gb = blockIdx.y;
    const int tx = threadIdx.x, ty = threadIdx.y;
    for (int rr = ty; rr < 32; rr += 8)
        tile[rr][tx] = gi[(size_t)(t * 32 + rr) * 1024 + gb * 32 + tx];
    __syncthreads();
    for (int gg = ty; gg < 32; gg += 8)
        gt[(size_t)(t * 1024 + gb * 32 + gg) * 32 + tx] = tile[tx][gg];
}

__global__ void init_h_kernel(const float* __restrict__ h0) {
    const int i = blockIdx.x * blockDim.x + threadIdx.x;
    const int r = i / HID, k = i % HID;
    ((float*)&g_hbuf[0][(k >> 1) * NENV + r])[k & 1] = h0[i];
}

// ---- persistent LSTM v3 ----
__global__ __launch_bounds__(256) void lstm_kernel(
        const float* __restrict__ gt, const float* __restrict__ done,
        const float* __restrict__ c0, const float* __restrict__ wh,
        float* __restrict__ outs) {
    extern __shared__ char smL[];
    ull*   hs2  = (ull*)smL;
    ull*   wt   = (ull*)(smL + 32768);
    float* gsmP = (float*)(smL + 40960);
    float* cs   = (float*)(smL + 49152);
    float* ms   = (float*)(smL + 49408);
    __shared__ int s_base;

    const int tid = threadIdx.x, blk = blockIdx.x;
    const int w = tid >> 5, lane = tid & 31;

    {
        const int G = (w & 3) * HID + 2 * blk + (w >> 2);
        const ull* whrow = (const ull*)(wh + (size_t)G * HID);
#pragma unroll
        for (int it = 0; it < 4; it++) {
            const int kp = lane + it * 32;
            wt[kp * 8 + w] = whrow[kp];
        }
    }
    const int hcl = (tid >> 5) & 1, r = lane;
    if (tid < 64) cs[tid] = c0[r * HID + 2 * blk + hcl];
    if (tid == 0) s_base = *(volatile int*)&g_flags[blk];
    __syncthreads();
    const int base = s_base;

    const int kb = w * 16;
    int Gj[4]; float giv[4];
    if (tid < 64) {
#pragma unroll
        for (int j = 0; j < 4; j++) {
            const int g = hcl * 4 + j;
            Gj[j] = (g & 3) * HID + 2 * blk + (g >> 2);
            giv[j] = __ldg(&gt[(size_t)Gj[j] * 32 + r]);
        }
    }

    for (int t = 0; t < TT; t++) {
        const float4* hsrc = (const float4*)g_hbuf[t & 1];
        if (tid < NENV) ms[tid] = 1.0f - done[t * NENV + tid];
#pragma unroll
        for (int i = 0; i < 8; i++)
            ((float4*)hs2)[tid + i * 256] = __ldcg(&hsrc[tid + i * 256]);
        __syncthreads();

        ull a[8];
#pragma unroll
        for (int g = 0; g < 8; g++) a[g] = 0ull;
#pragma unroll 4
        for (int i = 0; i < 16; i++) {
            const int kp = kb + i;
            const ull xv = hs2[kp * NENV + lane];
            const ulonglong2* wr = (const ulonglong2*)&wt[kp * 8];
            const ulonglong2 w01 = wr[0], w23 = wr[1], w45 = wr[2], w67 = wr[3];
            a[0] = ffma2(xv, w01.x, a[0]); a[1] = ffma2(xv, w01.y, a[1]);
            a[2] = ffma2(xv, w23.x, a[2]); a[3] = ffma2(xv, w23.y, a[3]);
            a[4] = ffma2(xv, w45.x, a[4]); a[5] = ffma2(xv, w45.y, a[5]);
            a[6] = ffma2(xv, w67.x, a[6]); a[7] = ffma2(xv, w67.y, a[7]);
        }
#pragma unroll
        for (int g = 0; g < 8; g++)
            gsmP[w * 256 + g * 32 + lane] = psum(a[g]);
        __syncthreads();

        ull* hdst = g_hbuf[(t + 1) & 1];
        float hval = 0.f;
        if (tid < 64) {
            const float m = ms[r];
            float gate[4];
#pragma unroll
            for (int j = 0; j < 4; j++) {
                const int g = hcl * 4 + j;
                float s = 0.f;
#pragma unroll
                for (int q = 0; q < 8; q++) s += gsmP[q * 256 + g * 32 + r];
                gate[j] = giv[j] + m * s;
            }
            const float iv = sig_fast(gate[0]);
            const float fv = sig_fast(gate[1]);
            const float gv = tanh_fast(gate[2]);
            const float ov = sig_fast(gate[3]);
            const float c = fv * (cs[tid] * m) + iv * gv;
            cs[tid] = c;
            hval = ov * tanh_fast(c);
            ((float*)&hdst[blk * NENV + r])[hcl] = hval;
            __threadfence();
        }
        __syncthreads();
        const int tgt = base + t + 1;
        if (tid == 0) *(volatile int*)&g_flags[blk] = tgt;
        if (tid < 64) {
            outs[(size_t)(t * NENV + r) * HID + 2 * blk + hcl] = hval;
            if (t + 1 < TT) {
#pragma unroll
                for (int j = 0; j < 4; j++)
                    giv[j] = __ldg(&gt[(size_t)((t + 1) * 1024 + Gj[j]) * 32 + r]);
            }
        }
        if (w == 0) {
#pragma unroll
            for (int q = 0; q < 4; q++)
                while (*(volatile int*)&g_flags[lane + q * 32] - tgt < 0)
                    __nanosleep(20);
        }
        __syncthreads();
    }
}

// ---- actor/critic heads ----
__global__ void heads_kernel(const float* __restrict__ outs,
                             const float* __restrict__ aw, const float* __restrict__ ab,
                             const float* __restrict__ cw, const float* __restrict__ cb,
                             float* __restrict__ out) {
    __shared__ float hsm[32 * HID];
    const int tid = threadIdx.x, row0 = blockIdx.x * 32;
    for (int i = tid; i < 32 * HID; i += 256) hsm[i] = outs[(size_t)row0 * HID + i];
    __syncthreads();
    for (int o = tid; o < 32 * 19; o += 256) {
        const int r = o / 19, j = o % 19;
        const float* wp = (j < 18) ? (aw + j * HID) : cw;
        const float bias = (j < 18) ? ab[j] : cb[0];
        const float4* h4 = (const float4*)(hsm + r * HID);
        const float4* w4 = (const float4*)wp;
        float acc = 0.f;
#pragma unroll 8
        for (int k = 0; k < HID / 4; k++) {
            const float4 hv = h4[k];
            const float4 wv = __ldg(&w4[k]);
            acc += hv.x*wv.x + hv.y*wv.y + hv.z*wv.z + hv.w*wv.w;
        }
        out[(size_t)(row0 + r) * 19 + j] = acc + bias;
    }
}

// ---- launch ----
extern "C" void kernel_launch(void* const* d_in, const int* in_sizes, int n_in,
                              void* d_out, int out_size) {
    const float* x    = (const float*)d_in[0];
    const float* done = (const float*)d_in[1];
    const float* h0   = (const float*)d_in[2];
    const float* c0   = (const float*)d_in[3];
    const float* c1w  = (const float*)d_in[4];
    const float* c1b  = (const float*)d_in[5];
    const float* c2w  = (const float*)d_in[6];
    const float* c2b  = (const float*)d_in[7];
    const float* c3w  = (const float*)d_in[8];
    const float* c3b  = (const float*)d_in[9];
    const float* fcw  = (const float*)d_in[10];
    const float* fcb  = (const float*)d_in[11];
    const float* wi   = (const float*)d_in[12];
    const float* wh   = (const float*)d_in[13];
    const float* bi   = (const float*)d_in[14];
    const float* bh   = (const float*)d_in[15];
    const float* aw   = (const float*)d_in[16];
    const float* ab   = (const float*)d_in[17];
    const float* cw   = (const float*)d_in[18];
    const float* cb   = (const float*)d_in[19];
    float* out = (float*)d_out;

    cudaFuncSetAttribute(conv1_kernel, cudaFuncAttributeMaxDynamicSharedMemorySize, 102400);
    cudaFuncSetAttribute(conv2_kernel, cudaFuncAttributeMaxDynamicSharedMemorySize, 102464);
    cudaFuncSetAttribute(conv3_kernel, cudaFuncAttributeMaxDynamicSharedMemorySize, 199680);
    cudaFuncSetAttribute(lstm_kernel,  cudaFuncAttributeMaxDynamicSharedMemorySize, 49664);

    float* out1;  cudaGetSymbolAddress((void**)&out1,  g_out1);
    float* out2;  cudaGetSymbolAddress((void**)&out2,  g_out2);
    float* out3;  cudaGetSymbolAddress((void**)&out3,  g_out3);
    float* feats; cudaGetSymbolAddress((void**)&feats, g_feats);
    float* gi;    cudaGetSymbolAddress((void**)&gi,    g_gi);
    float* gt;    cudaGetSymbolAddress((void**)&gt,    g_gt);
    float* outs;  cudaGetSymbolAddress((void**)&outs,  g_outs);
    ull* w3a;     cudaGetSymbolAddress((void**)&w3a,   g_w3a);
    ull* w3b;     cudaGetSymbolAddress((void**)&w3b,   g_w3b);

    conv1_kernel<<<TN, 256, 102400>>>(x, c1w, c1b, out1);
    prep_w3<<<48, 256>>>(c3w);
    conv2_kernel<<<TN / 2, 256, 102464>>>(out1, c2w, c2b, out2);
    conv3_kernel<<<TN / 8, 256, 199680>>>(out2, w3a, w3b, c3b, out3);   // 4th: profiled
    gemm_nt<<<dim3(512 / 128, TN / 128), 256>>>(out3, fcw, fcb, nullptr, feats, TN, 512, 1024, 1);
    gemm_nt<<<dim3(1024 / 128, TN / 128), 256>>>(feats, wi, bi, bh, gi, TN, 1024, 512, 0);
    gi_transpose<<<dim3(TT, 32), dim3(32, 8)>>>(gi, gt);
    init_h_kernel<<<32, 256>>>(h0);
    lstm_kernel<<<NBLK_LSTM, 256, 49664>>>(gt, done, c0, wh, outs);
    heads_kernel<<<TN / 32, 256>>>(outs, aw, ab, cw, cb, out);
}